// round 17
// baseline (speedup 1.0000x reference)
#include <cuda_runtime.h>
#include <cuda_fp16.h>
#include <cstdint>

#define NN 8192
#define FF 128
#define NEG 0.2f
#define KC 128                    // K-chunk (columns per iteration)
#define NSPLIT 4
#define NCHS (NN / KC / NSPLIT)   // 16 chunks per split
#define BROW 272                  // smem row pitch bytes (128 halves + 8 pad)

// ----------------------------- device scratch ------------------------------
__device__ float g_xp[(size_t)NN * FF];       // x' = x@W + b (fp32)
__device__ __half g_xht[(size_t)FF * NN];     // x'^T in f16 [f][j]
__device__ float g_ssrc[NN];
__device__ float g_sdst[NN];
__device__ float g_fac[3 * NN];               // ne | ne2 | nb
__device__ unsigned g_maxbits;
__device__ float g_pnum[(size_t)NSPLIT * NN * FF];
__device__ float g_pden[NSPLIT * NN];
__device__ uint4 g_adjb[(size_t)NN * 64];     // packed mask bits, 8MB (L2-hot)

// ----------------------------- helpers -------------------------------------
__device__ __forceinline__ uint32_t s2u(const void* p) {
    uint32_t a;
    asm("{ .reg .u64 t; cvta.to.shared.u64 t, %1; cvt.u32.u64 %0, t; }" : "=r"(a) : "l"(p));
    return a;
}
#define LDSM4(d0, d1, d2, d3, addr)                                           \
    asm volatile("ldmatrix.sync.aligned.m8n8.x4.shared.b16 {%0,%1,%2,%3}, [%4];" \
                 : "=r"(d0), "=r"(d1), "=r"(d2), "=r"(d3) : "r"(addr))
#define MMA16816(d0, d1, d2, d3, A0, A1, A2, A3, B0, B1)                      \
    asm volatile(                                                             \
        "mma.sync.aligned.m16n8k16.row.col.f32.f16.f16.f32 "                  \
        "{%0,%1,%2,%3}, {%4,%5,%6,%7}, {%8,%9}, {%0,%1,%2,%3};"               \
        : "+f"(d0), "+f"(d1), "+f"(d2), "+f"(d3)                              \
        : "r"(A0), "r"(A1), "r"(A2), "r"(A3), "r"(B0), "r"(B1))
#define CP16(dst, src)                                                        \
    asm volatile("cp.async.ca.shared.global [%0], [%1], 16;" :: "r"(dst), "l"(src) : "memory")
#define CPCOMMIT() asm volatile("cp.async.commit_group;" ::: "memory")
#define CPWAIT0()  asm volatile("cp.async.wait_group 0;" ::: "memory")

// ----------------------------- K0: pack adjacency to bits ------------------
// Plane-ballot layout: g_adjb[row*64 + ci].{x,y,z,w}; bit l of plane e
// corresponds to column ci*128 + 4*l + e. Diagonal folded in.
__global__ void __launch_bounds__(256, 8)
k_pack(const float* __restrict__ adj) {
    const int row = blockIdx.x * 8 + (threadIdx.x >> 5);
    const int lane = threadIdx.x & 31;
    const float4* src = (const float4*)(adj + (size_t)row * NN) + lane;
    uint4* dst = g_adjb + (size_t)row * 64;
#pragma unroll 4
    for (int it = 0; it < 64; ++it) {
        const float4 v = __ldg(src + it * 32);
        const int c0 = it * 128 + lane * 4;
        const unsigned b0 = __ballot_sync(0xffffffffu, v.x > 0.f || c0 + 0 == row);
        const unsigned b1 = __ballot_sync(0xffffffffu, v.y > 0.f || c0 + 1 == row);
        const unsigned b2 = __ballot_sync(0xffffffffu, v.z > 0.f || c0 + 2 == row);
        const unsigned b3 = __ballot_sync(0xffffffffu, v.w > 0.f || c0 + 3 == row);
        if (lane == 0) dst[it] = make_uint4(b0, b1, b2, b3);
    }
}

// ----------------------------- K1: x' = x@W + b (+init) --------------------
__global__ void k_gemm(const float* __restrict__ x, const float* __restrict__ w,
                       const float* __restrict__ bias) {
    __shared__ float ws[64][128];
    __shared__ float xs[32][64];
    const int tid = threadIdx.x;
    const int row0 = blockIdx.x * 32;
    if (blockIdx.x == 0 && tid == 0) g_maxbits = 0u;
    const int c = tid & 127;
    const int rr = tid >> 7;
    float acc[16];
#pragma unroll
    for (int q = 0; q < 16; ++q) acc[q] = 0.f;
    for (int kb = 0; kb < 128; kb += 64) {
        for (int t = tid; t < 64 * 128; t += 256)
            ws[t >> 7][t & 127] = w[(kb + (t >> 7)) * 128 + (t & 127)];
        for (int t = tid; t < 32 * 64; t += 256)
            xs[t >> 6][t & 63] = x[(size_t)(row0 + (t >> 6)) * 128 + kb + (t & 63)];
        __syncthreads();
#pragma unroll 4
        for (int kk = 0; kk < 64; ++kk) {
            float wv = ws[kk][c];
#pragma unroll
            for (int q = 0; q < 16; ++q) acc[q] += xs[rr * 16 + q][kk] * wv;
        }
        __syncthreads();
    }
    const float b = bias[c];
#pragma unroll
    for (int q = 0; q < 16; ++q)
        g_xp[(size_t)(row0 + rr * 16 + q) * 128 + c] = acc[q] + b;
}

// ----------------------------- K2: scores ----------------------------------
__global__ void k_score(const float* __restrict__ phi) {
    const int warp = threadIdx.x >> 5, lane = threadIdx.x & 31;
    const int i = blockIdx.x * 8 + warp;
    const float4* xr = (const float4*)(g_xp + (size_t)i * FF);
    const float4* pl = (const float4*)phi;
    const float4* ph = (const float4*)(phi + FF);
    float4 xv = xr[lane], a = pl[lane], b = ph[lane];
    float s1 = xv.x * a.x + xv.y * a.y + xv.z * a.z + xv.w * a.w;
    float s2 = xv.x * b.x + xv.y * b.y + xv.z * b.z + xv.w * b.w;
#pragma unroll
    for (int o = 16; o; o >>= 1) {
        s1 += __shfl_xor_sync(0xffffffffu, s1, o);
        s2 += __shfl_xor_sync(0xffffffffu, s2, o);
    }
    if (lane == 0) {
        g_ssrc[i] = s1;
        g_sdst[i] = s2;
        unsigned bits = __float_as_uint(s2);
        unsigned enc = bits ^ ((bits >> 31) ? 0xFFFFFFFFu : 0x80000000u);
        atomicMax(&g_maxbits, enc);
    }
}

// ----------------------------- K2b: factors + X'^T f16 (merged) ------------
__global__ void k_prep() {
    __shared__ float t[32][33];
    const int jb = blockIdx.x * 32, fb = blockIdx.y * 32;
    const int tx = threadIdx.x, ty = threadIdx.y;     // (32,8)
#pragma unroll
    for (int q = 0; q < 4; ++q)
        t[ty + q * 8][tx] = g_xp[(size_t)(jb + ty + q * 8) * 128 + fb + tx];
    __syncthreads();
#pragma unroll
    for (int q = 0; q < 4; ++q)
        g_xht[(size_t)(fb + ty + q * 8) * NN + jb + tx] = __float2half_rn(t[tx][ty + q * 8]);

    if (blockIdx.y == 0 && blockIdx.x < 32) {
        const int i = blockIdx.x * 256 + ty * 32 + tx;
        const unsigned u = g_maxbits;
        const float dmax = __uint_as_float(u ^ ((u >> 31) ? 0x80000000u : 0xFFFFFFFFu));
        const float d = g_sdst[i] - dmax;     // <= 0
        g_fac[i] = expf(d);
        g_fac[NN + i] = expf(NEG * d);
        g_fac[2 * NN + i] = d;
    }
}

// ----------------------------- K3: HMMA attention (split-K) ----------------
// SMEM: P(64 x 128 f16, pitch 272) | B0 | B1 (128 x 128 f16 each) | row consts
#define P_OFF  0
#define B0_OFF 17408
#define B1_OFF 52224
#define RC_OFF 87040
#define SMEM_TOTAL (RC_OFF + 3 * 64 * 4)

__global__ void __launch_bounds__(256, 2)
k_attn_hmma() {
    extern __shared__ __align__(16) char smem[];
    char* Pb = smem + P_OFF;
    float* sA  = (float*)(smem + RC_OFF);
    float* sE  = sA + 64;
    float* sE2 = sA + 128;

    const int tid = threadIdx.x;
    const int wid = tid >> 5, lane = tid & 31;
    const int i0 = blockIdx.x * 64;
    const int sp = blockIdx.y;
    const int rowbase = i0 + 8 * wid;

    const uint32_t uP = s2u(Pb);
    const uint32_t uB[2] = {s2u(smem + B0_OFF), s2u(smem + B1_OFF)};

    // ---- row constants ----
    if (tid < 64) {
        const int i = i0 + tid;
        const unsigned u = g_maxbits;
        const float dmax = __uint_as_float(u ^ ((u >> 31) ? 0x80000000u : 0xFFFFFFFFu));
        const float ra1 = g_ssrc[i] + dmax;
        const float mvv = ra1 > 0.f ? ra1 : NEG * ra1;
        sA[tid] = ra1;
        sE[tid] = expf(ra1 - mvv);
        sE2[tid] = expf(NEG * ra1 - mvv);
    }

    // ---- consumer fragment addressing (m16n64 per warp, proven R14) ----
    const int r0 = (wid & 3) * 16, n0 = (wid >> 2) * 64;
    const uint32_t aOff = (uint32_t)((r0 + (lane & 15)) * BROW + (lane >> 4) * 16);
    const uint32_t bOff = (uint32_t)((n0 + ((lane >> 4) << 3) + (lane & 7)) * BROW +
                                     ((lane >> 3) & 1) * 16);
    float acc[8][4];
#pragma unroll
    for (int nt = 0; nt < 8; ++nt)
#pragma unroll
        for (int k = 0; k < 4; ++k) acc[nt][k] = 0.f;
    float dacc[8];
#pragma unroll
    for (int rr = 0; rr < 8; ++rr) dacc[rr] = 0.f;

    // ---- B cp.async addressing ----
    const int bf0 = 16 * wid + (lane >> 4);
    const int bc16 = (lane & 15) * 16;

    // ---- prologue: B(0) + mask/fac prefetch(0) ----
    {
        const int j0 = sp * NCHS * KC;
#pragma unroll
        for (int p = 0; p < 8; ++p) {
            const int f = bf0 + 2 * p;
            CP16(uB[0] + f * BROW + bc16,
                 (const char*)g_xht + ((size_t)f * NN + j0) * 2 + bc16);
        }
        CPCOMMIT();
    }
    uint4 aw[8];
    float4 fne, fne2, fnb;
    {
        const int ci = sp * NCHS;
        const int j0 = ci * KC;
#pragma unroll
        for (int rr = 0; rr < 8; ++rr)
            aw[rr] = __ldg(g_adjb + (size_t)(rowbase + rr) * 64 + ci);
        fne  = __ldg((const float4*)(g_fac + j0) + lane);
        fne2 = __ldg((const float4*)(g_fac + NN + j0) + lane);
        fnb  = __ldg((const float4*)(g_fac + 2 * NN + j0) + lane);
    }
    CPWAIT0();
    __syncthreads();            // row consts + B0 visible

    // ---- build P(0) ----
#pragma unroll
    for (int rr = 0; rr < 8; ++rr) {
        const float ra1 = sA[8 * wid + rr];
        const float er = sE[8 * wid + rr], er2 = sE2[8 * wid + rr];
        const uint4 w = aw[rr];
        float p0 = (ra1 + fnb.x) > 0.f ? er * fne.x : er2 * fne2.x;
        float p1 = (ra1 + fnb.y) > 0.f ? er * fne.y : er2 * fne2.y;
        float p2 = (ra1 + fnb.z) > 0.f ? er * fne.z : er2 * fne2.z;
        float p3 = (ra1 + fnb.w) > 0.f ? er * fne.w : er2 * fne2.w;
        p0 = ((w.x >> lane) & 1u) ? p0 : 0.f;
        p1 = ((w.y >> lane) & 1u) ? p1 : 0.f;
        p2 = ((w.z >> lane) & 1u) ? p2 : 0.f;
        p3 = ((w.w >> lane) & 1u) ? p3 : 0.f;
        __half2 h01 = __floats2half2_rn(p0, p1);
        __half2 h23 = __floats2half2_rn(p2, p3);
        const float2 f01 = __half22float2(h01);
        const float2 f23 = __half22float2(h23);
        dacc[rr] += (f01.x + f01.y) + (f23.x + f23.y);
        uint2 st;
        st.x = *reinterpret_cast<uint32_t*>(&h01);
        st.y = *reinterpret_cast<uint32_t*>(&h23);
        *(uint2*)(Pb + (8 * wid + rr) * BROW + lane * 8) = st;
    }
    __syncthreads();            // P0 visible

    // ---- main loop (R14 two-phase structure) ----
    int buf = 0;
    for (int cs = 0; cs < NCHS; ++cs) {
        const bool more = (cs + 1 < NCHS);
        if (more) {
            const int cin = sp * NCHS + cs + 1;
            const int j0n = cin * KC;
#pragma unroll
            for (int p = 0; p < 8; ++p) {
                const int f = bf0 + 2 * p;
                CP16(uB[buf ^ 1] + f * BROW + bc16,
                     (const char*)g_xht + ((size_t)f * NN + j0n) * 2 + bc16);
            }
            CPCOMMIT();
#pragma unroll
            for (int rr = 0; rr < 8; ++rr)
                aw[rr] = __ldg(g_adjb + (size_t)(rowbase + rr) * 64 + cin);
            fne  = __ldg((const float4*)(g_fac + j0n) + lane);
            fne2 = __ldg((const float4*)(g_fac + NN + j0n) + lane);
            fnb  = __ldg((const float4*)(g_fac + 2 * NN + j0n) + lane);
        }

        // --- mma on chunk cs ---
        const uint32_t uBc = uB[buf];
#pragma unroll
        for (int ks = 0; ks < 8; ++ks) {
            const uint32_t k2 = ks * 32;
            uint32_t A0, A1, A2, A3;
            LDSM4(A0, A1, A2, A3, uP + aOff + k2);
#pragma unroll
            for (int p = 0; p < 4; ++p) {
                uint32_t B0, B1, B2, B3;
                LDSM4(B0, B1, B2, B3, uBc + bOff + p * (16 * BROW) + k2);
                MMA16816(acc[2 * p][0], acc[2 * p][1], acc[2 * p][2], acc[2 * p][3],
                         A0, A1, A2, A3, B0, B1);
                MMA16816(acc[2 * p + 1][0], acc[2 * p + 1][1], acc[2 * p + 1][2], acc[2 * p + 1][3],
                         A0, A1, A2, A3, B2, B3);
            }
        }
        CPWAIT0();
        __syncthreads();        // mma done reading P; B(c+1) landed

        if (more) {
#pragma unroll
            for (int rr = 0; rr < 8; ++rr) {
                const float ra1 = sA[8 * wid + rr];
                const float er = sE[8 * wid + rr], er2 = sE2[8 * wid + rr];
                const uint4 w = aw[rr];
                float p0 = (ra1 + fnb.x) > 0.f ? er * fne.x : er2 * fne2.x;
                float p1 = (ra1 + fnb.y) > 0.f ? er * fne.y : er2 * fne2.y;
                float p2 = (ra1 + fnb.z) > 0.f ? er * fne.z : er2 * fne2.z;
                float p3 = (ra1 + fnb.w) > 0.f ? er * fne.w : er2 * fne2.w;
                p0 = ((w.x >> lane) & 1u) ? p0 : 0.f;
                p1 = ((w.y >> lane) & 1u) ? p1 : 0.f;
                p2 = ((w.z >> lane) & 1u) ? p2 : 0.f;
                p3 = ((w.w >> lane) & 1u) ? p3 : 0.f;
                __half2 h01 = __floats2half2_rn(p0, p1);
                __half2 h23 = __floats2half2_rn(p2, p3);
                const float2 f01 = __half22float2(h01);
                const float2 f23 = __half22float2(h23);
                dacc[rr] += (f01.x + f01.y) + (f23.x + f23.y);
                uint2 st;
                st.x = *reinterpret_cast<uint32_t*>(&h01);
                st.y = *reinterpret_cast<uint32_t*>(&h23);
                *(uint2*)(Pb + (8 * wid + rr) * BROW + lane * 8) = st;
            }
            __syncthreads();    // P(c+1) visible
        }
        buf ^= 1;
    }

    // ---- denominator partials (warp-reduce, fixed order) ----
#pragma unroll
    for (int rr = 0; rr < 8; ++rr) {
        float v = dacc[rr];
#pragma unroll
        for (int o = 16; o; o >>= 1) v += __shfl_xor_sync(0xffffffffu, v, o);
        if (lane == 0) g_pden[sp * NN + rowbase + rr] = v;
    }

    // ---- numerator partials ----
    float* pnum = g_pnum + (size_t)sp * NN * FF;
    const int gg = lane >> 2, cc = lane & 3;
    const int ra = r0 + gg, rb = r0 + gg + 8;
#pragma unroll
    for (int nt = 0; nt < 8; ++nt) {
        const int col = n0 + nt * 8 + 2 * cc;
        *(float2*)(pnum + (size_t)(i0 + ra) * FF + col) = make_float2(acc[nt][0], acc[nt][1]);
        *(float2*)(pnum + (size_t)(i0 + rb) * FF + col) = make_float2(acc[nt][2], acc[nt][3]);
    }
}

// ----------------------------- K4: split-K combine -------------------------
__global__ void k_combine(float* __restrict__ out) {
    const int idx = blockIdx.x * 256 + threadIdx.x;
    const int i = idx >> 7;
    const float den = (g_pden[i] + g_pden[NN + i]) +
                      (g_pden[2 * NN + i] + g_pden[3 * NN + i]);
    const size_t o = (size_t)idx;
    const float num = (g_pnum[o] + g_pnum[(size_t)NN * FF + o]) +
                      (g_pnum[2 * (size_t)NN * FF + o] + g_pnum[3 * (size_t)NN * FF + o]);
    out[o] = num / den;
}

// ---------------------------------------------------------------------------
extern "C" void kernel_launch(void* const* d_in, const int* in_sizes, int n_in,
                              void* d_out, int out_size) {
    const float* adj  = (const float*)d_in[0];
    const float* x    = (const float*)d_in[1];
    const float* w    = (const float*)d_in[2];
    const float* bias = (const float*)d_in[3];
    const float* phi  = (const float*)d_in[4];
    float* out = (float*)d_out;

    cudaFuncSetAttribute(k_attn_hmma, cudaFuncAttributeMaxDynamicSharedMemorySize,
                         SMEM_TOTAL);

    k_pack<<<NN / 8, 256>>>(adj);
    k_gemm<<<NN / 32, 256>>>(x, w, bias);
    k_score<<<NN / 8, 256>>>(phi);
    {
        dim3 b(32, 8), g(NN / 32, FF / 32);
        k_prep<<<g, b>>>();
    }
    {
        dim3 g(NN / 64, NSPLIT);
        k_attn_hmma<<<g, 256, SMEM_TOTAL>>>();
    }
    k_combine<<<NN * FF / 256, 256>>>(out);
}